// round 12
// baseline (speedup 1.0000x reference)
#include <cuda_runtime.h>
#include <cuda_bf16.h>
#include <cstdint>

// ---------------------------------------------------------------------------
// GraphAttentionLayer: N=4096, F=512, H=8, d=64
//  1) cvt_kernel:  x, Wq/Wk/Wv f32 -> bf16 globals
//  2) proj_kernel: Q/K/V bf16 GEMM (cp.async 2-stage)
//  3) attn_kernel: flash attention, raw adj fused in-loop and SOFTWARE-
//     PIPELINED ONE TILE AHEAD (persistent int2 regs, reload right after
//     consumption); PV split into n-halves to stay under 128 regs; 4-stage
//     cp.async K/V ring, one __syncthreads per tile, fixed-max base-2 softmax.
// ---------------------------------------------------------------------------

#define NN 4096
#define FF 512
#define NH 8
#define HD 64

__device__ __nv_bfloat16 g_Q[NN * FF];
__device__ __nv_bfloat16 g_K[NN * FF];
__device__ __nv_bfloat16 g_V[NN * FF];
__device__ __nv_bfloat16 g_xb[NN * FF];
__device__ __nv_bfloat16 g_Wb[3 * FF * FF];

__device__ __forceinline__ uint32_t smem_u32(const void* p) {
    return (uint32_t)__cvta_generic_to_shared(p);
}
__device__ __forceinline__ void ldsm_x4(uint32_t addr, uint32_t& r0, uint32_t& r1,
                                        uint32_t& r2, uint32_t& r3) {
    asm volatile("ldmatrix.sync.aligned.m8n8.x4.shared.b16 {%0,%1,%2,%3}, [%4];"
                 : "=r"(r0), "=r"(r1), "=r"(r2), "=r"(r3) : "r"(addr));
}
__device__ __forceinline__ void ldsm_x4_t(uint32_t addr, uint32_t& r0, uint32_t& r1,
                                          uint32_t& r2, uint32_t& r3) {
    asm volatile("ldmatrix.sync.aligned.m8n8.x4.trans.shared.b16 {%0,%1,%2,%3}, [%4];"
                 : "=r"(r0), "=r"(r1), "=r"(r2), "=r"(r3) : "r"(addr));
}
__device__ __forceinline__ void mma16816(float* d, const uint32_t* a, uint32_t b0, uint32_t b1) {
    asm volatile("mma.sync.aligned.m16n8k16.row.col.f32.bf16.bf16.f32 "
                 "{%0,%1,%2,%3}, {%4,%5,%6,%7}, {%8,%9}, {%0,%1,%2,%3};"
                 : "+f"(d[0]), "+f"(d[1]), "+f"(d[2]), "+f"(d[3])
                 : "r"(a[0]), "r"(a[1]), "r"(a[2]), "r"(a[3]), "r"(b0), "r"(b1));
}
__device__ __forceinline__ uint32_t packbf(float lo, float hi) {
    uint32_t r;
    asm("cvt.rn.bf16x2.f32 %0, %1, %2;" : "=r"(r) : "f"(hi), "f"(lo));
    return r;
}
__device__ __forceinline__ float ex2(float x) {
    float r;
    asm("ex2.approx.ftz.f32 %0, %1;" : "=f"(r) : "f"(x));
    return r;
}
__device__ __forceinline__ void cp16(void* s, const void* g) {
    asm volatile("cp.async.cg.shared.global [%0], [%1], 16;"
                 :: "r"(smem_u32(s)), "l"(g));
}
__device__ __forceinline__ void cp_commit() { asm volatile("cp.async.commit_group;"); }
template <int n>
__device__ __forceinline__ void cp_wait() { asm volatile("cp.async.wait_group %0;" :: "n"(n)); }

// ---------------------------------------------------------------------------
// cvt: f32 -> bf16 for x and Wq/Wk/Wv.
// ---------------------------------------------------------------------------
#define XN4 (NN * FF / 4)
#define WN4 (FF * FF / 4)
#define CVT_TOTAL (XN4 + 3 * WN4)

__global__ __launch_bounds__(256) void cvt_kernel(const float* __restrict__ x,
                                                  const float* __restrict__ Wq,
                                                  const float* __restrict__ Wk,
                                                  const float* __restrict__ Wv) {
    const int i = blockIdx.x * 256 + threadIdx.x;
    if (i >= CVT_TOTAL) return;
    const float* src;
    __nv_bfloat16* dst;
    int off;
    if (i < XN4) {
        src = x; dst = g_xb; off = i;
    } else {
        const int j = i - XN4;
        const int m = j / WN4;
        off = j - m * WN4;
        src = (m == 0) ? Wq : (m == 1) ? Wk : Wv;
        dst = g_Wb + m * (FF * FF);
    }
    float4 v = __ldg((const float4*)src + off);
    uint2 st;
    st.x = packbf(v.x, v.y);
    st.y = packbf(v.z, v.w);
    *((uint2*)dst + off) = st;
}

// ---------------------------------------------------------------------------
// Projection GEMM (bf16): tile 128x128x64, cp.async 2-stage. grid (32,12).
// ---------------------------------------------------------------------------
#define PJ_ST (128 * 72)
#define PROJ_SMEM (4 * PJ_ST * 2)

__global__ __launch_bounds__(256) void proj_kernel() {
    extern __shared__ __nv_bfloat16 ps[];
    __nv_bfloat16* sA = ps;
    __nv_bfloat16* sB = ps + 2 * PJ_ST;

    const int tid = threadIdx.x;
    const int lane = tid & 31;
    const int warp = tid >> 5;
    const int wr = warp & 3;
    const int wc = warp >> 2;
    const int mblk = blockIdx.x;
    const int mat = blockIdx.y >> 2;
    const int nblk = blockIdx.y & 3;

    const __nv_bfloat16* Ab = g_xb + (size_t)(mblk * 128) * FF;
    const __nv_bfloat16* Bb = g_Wb + (size_t)mat * FF * FF + (size_t)(nblk * 128) * FF;
    __nv_bfloat16* dst = (mat == 0) ? g_Q : (mat == 1) ? g_K : g_V;
    // Q scale = 1/sqrt(512) * log2(e)   (softmax in base-2)
    const float scale = (mat == 0) ? (0.044194173824159216f * 1.4426950408889634f) : 1.0f;

    float acc[2][8][4];
#pragma unroll
    for (int mt = 0; mt < 2; ++mt)
#pragma unroll
        for (int t = 0; t < 8; ++t)
#pragma unroll
            for (int i = 0; i < 4; ++i) acc[mt][t][i] = 0.f;

    const int lr = tid >> 3;
    const int lc8 = (tid & 7) * 8;

    auto load_tile = [&](int st, int kt) {
        const int k0 = kt * 64;
#pragma unroll
        for (int p = 0; p < 4; ++p) {
            const int r = lr + p * 32;
            cp16(&sA[st * PJ_ST + r * 72 + lc8], Ab + (size_t)r * FF + k0 + lc8);
            cp16(&sB[st * PJ_ST + r * 72 + lc8], Bb + (size_t)r * FF + k0 + lc8);
        }
        cp_commit();
    };

    load_tile(0, 0);

    for (int kt = 0; kt < 8; ++kt) {
        const int cur = kt & 1;
        if (kt < 7) {
            load_tile(cur ^ 1, kt + 1);
            cp_wait<1>();
        } else {
            cp_wait<0>();
        }
        __syncthreads();

        const __nv_bfloat16* sAc = sA + cur * PJ_ST;
        const __nv_bfloat16* sBc = sB + cur * PJ_ST;
#pragma unroll
        for (int ks = 0; ks < 4; ++ks) {
            uint32_t af[2][4];
#pragma unroll
            for (int mt = 0; mt < 2; ++mt) {
                const int row = wr * 32 + mt * 16 + (lane & 7) + ((lane >> 3) & 1) * 8;
                const int col = ks * 16 + (lane >> 4) * 8;
                ldsm_x4(smem_u32(&sAc[row * 72 + col]), af[mt][0], af[mt][1], af[mt][2], af[mt][3]);
            }
#pragma unroll
            for (int g = 0; g < 4; ++g) {
                const int row = wc * 64 + g * 16 + (lane & 7) + (lane >> 4) * 8;
                const int col = ks * 16 + ((lane >> 3) & 1) * 8;
                uint32_t b0, b1, b2, b3;
                ldsm_x4(smem_u32(&sBc[row * 72 + col]), b0, b1, b2, b3);
#pragma unroll
                for (int mt = 0; mt < 2; ++mt) {
                    mma16816(acc[mt][2 * g],     af[mt], b0, b1);
                    mma16816(acc[mt][2 * g + 1], af[mt], b2, b3);
                }
            }
        }
        __syncthreads();
    }

#pragma unroll
    for (int mt = 0; mt < 2; ++mt) {
        const int row = mblk * 128 + wr * 32 + mt * 16 + (lane >> 2);
#pragma unroll
        for (int t = 0; t < 8; ++t) {
            const int col = nblk * 128 + wc * 64 + t * 8 + (lane & 3) * 2;
            *(uint32_t*)&dst[(size_t)row * FF + col] =
                packbf(acc[mt][t][0] * scale, acc[mt][t][1] * scale);
            *(uint32_t*)&dst[(size_t)(row + 8) * FF + col] =
                packbf(acc[mt][t][2] * scale, acc[mt][t][3] * scale);
        }
    }
}

// ---------------------------------------------------------------------------
// Fused flash attention, adj software-pipelined one tile ahead.
// grid=(32,8), 256 threads (8 warps x 16 q rows), 2 CTAs/SM.
// Per tile: S half0 -> mask0 -> PV kg01 -> reload adj0 -> S half1 -> mask1
//           -> PV kg23 -> reload adj1.  Reloads land ~2500 cyc before use.
// ---------------------------------------------------------------------------
#define ST_BYTES (64 * 72 * 2)
#define ATTN_SMEM (8 * ST_BYTES)

__global__ __launch_bounds__(256, 2) void attn_kernel(const float* __restrict__ x,
                                                      const int* __restrict__ adj,
                                                      float* __restrict__ out) {
    extern __shared__ char sm[];
    __nv_bfloat16* sK = (__nv_bfloat16*)sm;                      // [4][64][72]
    __nv_bfloat16* sV = (__nv_bfloat16*)(sm + 4 * ST_BYTES);     // [4][64][72]

    const int tid = threadIdx.x;
    const int lane = tid & 31;
    const int warp = tid >> 5;
    const int q0 = blockIdx.x * 128;
    const int h = blockIdx.y;
    const int hc = h * HD;

    const int lr = tid >> 3;           // 0..31
    const int lc8 = (tid & 7) * 8;     // 0..56

    // --- stage Q (128 x 64, stride 72) through sK rows, grab frags ---
#pragma unroll
    for (int p = 0; p < 4; ++p) {
        const int r = lr + p * 32;
        uint4 v = *(const uint4*)(g_Q + (size_t)(q0 + r) * FF + hc + lc8);
        *(uint4*)&sK[r * 72 + lc8] = v;
    }
    __syncthreads();

    const int rw = warp * 16;
    uint32_t qf[4][4];
#pragma unroll
    for (int ks = 0; ks < 4; ++ks) {
        const int row = rw + (lane & 7) + ((lane >> 3) & 1) * 8;
        const int col = ks * 16 + (lane >> 4) * 8;
        ldsm_x4(smem_u32(&sK[row * 72 + col]), qf[ks][0], qf[ks][1], qf[ks][2], qf[ks][3]);
    }
    __syncthreads();   // Q frags extracted; stages may be overwritten

    float O[8][4];
#pragma unroll
    for (int t = 0; t < 8; ++t)
#pragma unroll
        for (int i = 0; i < 4; ++i) O[t][i] = 0.f;

    float l0 = 0.f, l1 = 0.f;

    const int ci = lane & 3;
    const int rl0 = rw + (lane >> 2);
    const int r0g = q0 + rl0;
    const int2* A0 = (const int2*)(adj + ((size_t)h * NN + r0g) * NN) + ci;
    const int2* A1 = A0 + 8 * (NN / 2);

    // prologue: async-load K/V tiles 0 and 1 into stages 0, 1
#pragma unroll
    for (int pre = 0; pre < 2; ++pre) {
        __nv_bfloat16* sKs = sK + pre * 64 * 72;
        __nv_bfloat16* sVs = sV + pre * 64 * 72;
#pragma unroll
        for (int p = 0; p < 2; ++p) {
            const int r = lr + p * 32;
            cp16(&sKs[r * 72 + lc8], g_K + (size_t)(pre * 64 + r) * FF + hc + lc8);
            cp16(&sVs[r * 72 + lc8], g_V + (size_t)(pre * 64 + r) * FF + hc + lc8);
        }
        cp_commit();
    }

    // prologue: adj tile 0 into persistent regs (half0: a*, half1: c*)
    int2 a0[4], a1[4], c0[4], c1[4];
#pragma unroll
    for (int t = 0; t < 4; ++t) {
        a0[t] = A0[t * 4];
        a1[t] = A1[t * 4];
        c0[t] = A0[16 + t * 4];
        c1[t] = A1[16 + t * 4];
    }

    for (int jt = 0; jt < 64; ++jt) {
        const int stg = jt & 3;

        if (jt < 62) {
            const int j2 = (jt + 2) * 64;
            const int ns = (jt + 2) & 3;
            __nv_bfloat16* sKs = sK + ns * 64 * 72;
            __nv_bfloat16* sVs = sV + ns * 64 * 72;
#pragma unroll
            for (int p = 0; p < 2; ++p) {
                const int r = lr + p * 32;
                cp16(&sKs[r * 72 + lc8], g_K + (size_t)(j2 + r) * FF + hc + lc8);
                cp16(&sVs[r * 72 + lc8], g_V + (size_t)(j2 + r) * FF + hc + lc8);
            }
            cp_commit();
            cp_wait<2>();
        } else if (jt == 62) {
            cp_wait<1>();
        } else {
            cp_wait<0>();
        }
        __syncthreads();   // the ONLY barrier in the tile

        const __nv_bfloat16* sKc = sK + stg * 64 * 72;
        const __nv_bfloat16* sVc = sV + stg * 64 * 72;
        const int2* A0n = A0 + (jt + 1) * 32;   // next tile (64 ints = 32 int2)
        const int2* A1n = A1 + (jt + 1) * 32;

        float s[4][4];
        uint32_t pk[8];

        // ---- S half0: n groups g=0,1 ----
#pragma unroll
        for (int t = 0; t < 4; ++t)
#pragma unroll
            for (int i = 0; i < 4; ++i) s[t][i] = 0.f;
#pragma unroll
        for (int ks = 0; ks < 4; ++ks) {
#pragma unroll
            for (int g = 0; g < 2; ++g) {
                const int row = g * 16 + (lane & 7) + (lane >> 4) * 8;
                const int col = ks * 16 + ((lane >> 3) & 1) * 8;
                uint32_t b0, b1, b2, b3;
                ldsm_x4(smem_u32(&sKc[row * 72 + col]), b0, b1, b2, b3);
                mma16816(s[2 * g],     qf[ks], b0, b1);
                mma16816(s[2 * g + 1], qf[ks], b2, b3);
            }
        }

        // ---- mask + exp half0 (adj loaded LAST tile) ----
#pragma unroll
        for (int t = 0; t < 4; ++t) {
            float p00 = ex2(s[t][0]);
            float p01 = ex2(s[t][1]);
            float p10 = ex2(s[t][2]);
            float p11 = ex2(s[t][3]);
            p00 = (a0[t].x > 0) ? p00 : 0.f;
            p01 = (a0[t].y > 0) ? p01 : 0.f;
            p10 = (a1[t].x > 0) ? p10 : 0.f;
            p11 = (a1[t].y > 0) ? p11 : 0.f;
            l0 += p00 + p01;
            l1 += p10 + p11;
            pk[2 * t]     = packbf(p00, p01);
            pk[2 * t + 1] = packbf(p10, p11);
        }

        // ---- PV half0: kg=0,1 (V rows 0..31 = n half0) ----
#pragma unroll
        for (int kg = 0; kg < 2; ++kg) {
            uint32_t pa[4];
            pa[0] = pk[4 * kg];
            pa[1] = pk[4 * kg + 1];
            pa[2] = pk[4 * kg + 2];
            pa[3] = pk[4 * kg + 3];
#pragma unroll
            for (int dg = 0; dg < 4; ++dg) {
                const int row = kg * 16 + (lane & 7) + ((lane >> 3) & 1) * 8;
                const int col = dg * 16 + (lane >> 4) * 8;
                uint32_t b0, b1, b2, b3;
                ldsm_x4_t(smem_u32(&sVc[row * 72 + col]), b0, b1, b2, b3);
                mma16816(O[2 * dg],     pa, b0, b1);
                mma16816(O[2 * dg + 1], pa, b2, b3);
            }
        }

        // ---- reload adj half0 for NEXT tile (used ~2500 cyc from now) ----
        if (jt < 63) {
#pragma unroll
            for (int t = 0; t < 4; ++t) {
                a0[t] = A0n[t * 4];
                a1[t] = A1n[t * 4];
            }
        }

        // ---- S half1: n groups g=2,3 ----
#pragma unroll
        for (int t = 0; t < 4; ++t)
#pragma unroll
            for (int i = 0; i < 4; ++i) s[t][i] = 0.f;
#pragma unroll
        for (int ks = 0; ks < 4; ++ks) {
#pragma unroll
            for (int g = 2; g < 4; ++g) {
                const int row = g * 16 + (lane & 7) + (lane >> 4) * 8;
                const int col = ks * 16 + ((lane >> 3) & 1) * 8;
                uint32_t b0, b1, b2, b3;
                ldsm_x4(smem_u32(&sKc[row * 72 + col]), b0, b1, b2, b3);
                mma16816(s[2 * (g - 2)],     qf[ks], b0, b1);
                mma16816(s[2 * (g - 2) + 1], qf[ks], b2, b3);
            }
        }

        // ---- mask + exp half1 ----
#pragma unroll
        for (int t = 0; t < 4; ++t) {
            float p00 = ex2(s[t][0]);
            float p01 = ex2(s[t][1]);
            float p10 = ex2(s[t][2]);
            float p11 = ex2(s[t][3]);
            p00 = (c0[t].x > 0) ? p00 : 0.f;
            p01 = (c0[t].y > 0) ? p01 : 0.f;
            p10 = (c1[t].x > 0) ? p10 : 0.f;
            p11 = (c1[t].y > 0) ? p11 : 0.f;
            l0 += p00 + p01;
            l1 += p10 + p11;
            pk[2 * t]     = packbf(p00, p01);
            pk[2 * t + 1] = packbf(p10, p11);
        }

        // ---- PV half1: kg=2,3 (V rows 32..63 = n half1) ----
#pragma unroll
        for (int kg = 2; kg < 4; ++kg) {
            uint32_t pa[4];
            pa[0] = pk[4 * (kg - 2)];
            pa[1] = pk[4 * (kg - 2) + 1];
            pa[2] = pk[4 * (kg - 2) + 2];
            pa[3] = pk[4 * (kg - 2) + 3];
#pragma unroll
            for (int dg = 0; dg < 4; ++dg) {
                const int row = kg * 16 + (lane & 7) + ((lane >> 3) & 1) * 8;
                const int col = dg * 16 + (lane >> 4) * 8;
                uint32_t b0, b1, b2, b3;
                ldsm_x4_t(smem_u32(&sVc[row * 72 + col]), b0, b1, b2, b3);
                mma16816(O[2 * dg],     pa, b0, b1);
                mma16816(O[2 * dg + 1], pa, b2, b3);
            }
        }

        // ---- reload adj half1 for NEXT tile ----
        if (jt < 63) {
#pragma unroll
            for (int t = 0; t < 4; ++t) {
                c0[t] = A0n[16 + t * 4];
                c1[t] = A1n[16 + t * 4];
            }
        }
        // no trailing barrier: 4-stage ring makes it unnecessary
    }

    // reduce l over the quad, then epilogue: normalize, residual, ELU
    l0 += __shfl_xor_sync(0xffffffffu, l0, 1);
    l0 += __shfl_xor_sync(0xffffffffu, l0, 2);
    l1 += __shfl_xor_sync(0xffffffffu, l1, 1);
    l1 += __shfl_xor_sync(0xffffffffu, l1, 2);
    const float inv0 = 1.f / l0;
    const float inv1 = 1.f / l1;
    const int r0 = r0g;
    const int r1 = r0 + 8;
#pragma unroll
    for (int t = 0; t < 8; ++t) {
        const int col = hc + t * 8 + ci * 2;
        float2 x0 = *(const float2*)(x + (size_t)r0 * FF + col);
        float2 x1 = *(const float2*)(x + (size_t)r1 * FF + col);
        float v00 = O[t][0] * inv0 + x0.x;
        float v01 = O[t][1] * inv0 + x0.y;
        float v10 = O[t][2] * inv1 + x1.x;
        float v11 = O[t][3] * inv1 + x1.y;
        v00 = (v00 > 0.f) ? v00 : expm1f(v00);
        v01 = (v01 > 0.f) ? v01 : expm1f(v01);
        v10 = (v10 > 0.f) ? v10 : expm1f(v10);
        v11 = (v11 > 0.f) ? v11 : expm1f(v11);
        *(float2*)(out + (size_t)r0 * FF + col) = make_float2(v00, v01);
        *(float2*)(out + (size_t)r1 * FF + col) = make_float2(v10, v11);
    }
}

extern "C" void kernel_launch(void* const* d_in, const int* in_sizes, int n_in,
                              void* d_out, int out_size) {
    const float* x  = (const float*)d_in[0];
    const float* Wq = (const float*)d_in[1];
    const float* Wk = (const float*)d_in[2];
    const float* Wv = (const float*)d_in[3];
    const int* adj  = (const int*)d_in[4];
    float* out = (float*)d_out;

    cudaFuncSetAttribute(proj_kernel, cudaFuncAttributeMaxDynamicSharedMemorySize, PROJ_SMEM);
    cudaFuncSetAttribute(attn_kernel, cudaFuncAttributeMaxDynamicSharedMemorySize, ATTN_SMEM);

    cvt_kernel<<<2816, 256>>>(x, Wq, Wk, Wv);
    proj_kernel<<<dim3(32, 12), 256, PROJ_SMEM>>>();
    attn_kernel<<<dim3(32, 8), 256, ATTN_SMEM>>>(x, adj, out);
}

// round 13
// speedup vs baseline: 1.0952x; 1.0952x over previous
#include <cuda_runtime.h>
#include <cuda_bf16.h>
#include <cstdint>

// ---------------------------------------------------------------------------
// GraphAttentionLayer: N=4096, F=512, H=8, d=64
//  1) cvt_kernel:  x, Wq/Wk/Wv f32 -> bf16 globals
//  2) proj_kernel: Q/K/V bf16 GEMM (cp.async 2-stage)
//  3) attn_kernel: flash attention; adj streamed through smem via COALESCED
//     cp.async (16 thr/row -> 4 lines/instr), 2-stage adj + 2-stage K/V rings
//     sharing commit groups, 1-tile-ahead prefetch, 2 syncs/tile, fixed-max
//     base-2 softmax. No adj register pressure.
// ---------------------------------------------------------------------------

#define NN 4096
#define FF 512
#define NH 8
#define HD 64

__device__ __nv_bfloat16 g_Q[NN * FF];
__device__ __nv_bfloat16 g_K[NN * FF];
__device__ __nv_bfloat16 g_V[NN * FF];
__device__ __nv_bfloat16 g_xb[NN * FF];
__device__ __nv_bfloat16 g_Wb[3 * FF * FF];

__device__ __forceinline__ uint32_t smem_u32(const void* p) {
    return (uint32_t)__cvta_generic_to_shared(p);
}
__device__ __forceinline__ void ldsm_x4(uint32_t addr, uint32_t& r0, uint32_t& r1,
                                        uint32_t& r2, uint32_t& r3) {
    asm volatile("ldmatrix.sync.aligned.m8n8.x4.shared.b16 {%0,%1,%2,%3}, [%4];"
                 : "=r"(r0), "=r"(r1), "=r"(r2), "=r"(r3) : "r"(addr));
}
__device__ __forceinline__ void ldsm_x4_t(uint32_t addr, uint32_t& r0, uint32_t& r1,
                                          uint32_t& r2, uint32_t& r3) {
    asm volatile("ldmatrix.sync.aligned.m8n8.x4.trans.shared.b16 {%0,%1,%2,%3}, [%4];"
                 : "=r"(r0), "=r"(r1), "=r"(r2), "=r"(r3) : "r"(addr));
}
__device__ __forceinline__ void mma16816(float* d, const uint32_t* a, uint32_t b0, uint32_t b1) {
    asm volatile("mma.sync.aligned.m16n8k16.row.col.f32.bf16.bf16.f32 "
                 "{%0,%1,%2,%3}, {%4,%5,%6,%7}, {%8,%9}, {%0,%1,%2,%3};"
                 : "+f"(d[0]), "+f"(d[1]), "+f"(d[2]), "+f"(d[3])
                 : "r"(a[0]), "r"(a[1]), "r"(a[2]), "r"(a[3]), "r"(b0), "r"(b1));
}
__device__ __forceinline__ uint32_t packbf(float lo, float hi) {
    uint32_t r;
    asm("cvt.rn.bf16x2.f32 %0, %1, %2;" : "=r"(r) : "f"(hi), "f"(lo));
    return r;
}
__device__ __forceinline__ float ex2(float x) {
    float r;
    asm("ex2.approx.ftz.f32 %0, %1;" : "=f"(r) : "f"(x));
    return r;
}
__device__ __forceinline__ void cp16(void* s, const void* g) {
    asm volatile("cp.async.cg.shared.global [%0], [%1], 16;"
                 :: "r"(smem_u32(s)), "l"(g));
}
__device__ __forceinline__ void cp_commit() { asm volatile("cp.async.commit_group;"); }
template <int n>
__device__ __forceinline__ void cp_wait() { asm volatile("cp.async.wait_group %0;" :: "n"(n)); }

// ---------------------------------------------------------------------------
// cvt: f32 -> bf16 for x and Wq/Wk/Wv.
// ---------------------------------------------------------------------------
#define XN4 (NN * FF / 4)
#define WN4 (FF * FF / 4)
#define CVT_TOTAL (XN4 + 3 * WN4)

__global__ __launch_bounds__(256) void cvt_kernel(const float* __restrict__ x,
                                                  const float* __restrict__ Wq,
                                                  const float* __restrict__ Wk,
                                                  const float* __restrict__ Wv) {
    const int i = blockIdx.x * 256 + threadIdx.x;
    if (i >= CVT_TOTAL) return;
    const float* src;
    __nv_bfloat16* dst;
    int off;
    if (i < XN4) {
        src = x; dst = g_xb; off = i;
    } else {
        const int j = i - XN4;
        const int m = j / WN4;
        off = j - m * WN4;
        src = (m == 0) ? Wq : (m == 1) ? Wk : Wv;
        dst = g_Wb + m * (FF * FF);
    }
    float4 v = __ldg((const float4*)src + off);
    uint2 st;
    st.x = packbf(v.x, v.y);
    st.y = packbf(v.z, v.w);
    *((uint2*)dst + off) = st;
}

// ---------------------------------------------------------------------------
// Projection GEMM (bf16): tile 128x128x64, cp.async 2-stage. grid (32,12).
// ---------------------------------------------------------------------------
#define PJ_ST (128 * 72)
#define PROJ_SMEM (4 * PJ_ST * 2)

__global__ __launch_bounds__(256) void proj_kernel() {
    extern __shared__ __nv_bfloat16 ps[];
    __nv_bfloat16* sA = ps;
    __nv_bfloat16* sB = ps + 2 * PJ_ST;

    const int tid = threadIdx.x;
    const int lane = tid & 31;
    const int warp = tid >> 5;
    const int wr = warp & 3;
    const int wc = warp >> 2;
    const int mblk = blockIdx.x;
    const int mat = blockIdx.y >> 2;
    const int nblk = blockIdx.y & 3;

    const __nv_bfloat16* Ab = g_xb + (size_t)(mblk * 128) * FF;
    const __nv_bfloat16* Bb = g_Wb + (size_t)mat * FF * FF + (size_t)(nblk * 128) * FF;
    __nv_bfloat16* dst = (mat == 0) ? g_Q : (mat == 1) ? g_K : g_V;
    // Q scale = 1/sqrt(512) * log2(e)   (softmax in base-2)
    const float scale = (mat == 0) ? (0.044194173824159216f * 1.4426950408889634f) : 1.0f;

    float acc[2][8][4];
#pragma unroll
    for (int mt = 0; mt < 2; ++mt)
#pragma unroll
        for (int t = 0; t < 8; ++t)
#pragma unroll
            for (int i = 0; i < 4; ++i) acc[mt][t][i] = 0.f;

    const int lr = tid >> 3;
    const int lc8 = (tid & 7) * 8;

    auto load_tile = [&](int st, int kt) {
        const int k0 = kt * 64;
#pragma unroll
        for (int p = 0; p < 4; ++p) {
            const int r = lr + p * 32;
            cp16(&sA[st * PJ_ST + r * 72 + lc8], Ab + (size_t)r * FF + k0 + lc8);
            cp16(&sB[st * PJ_ST + r * 72 + lc8], Bb + (size_t)r * FF + k0 + lc8);
        }
        cp_commit();
    };

    load_tile(0, 0);

    for (int kt = 0; kt < 8; ++kt) {
        const int cur = kt & 1;
        if (kt < 7) {
            load_tile(cur ^ 1, kt + 1);
            cp_wait<1>();
        } else {
            cp_wait<0>();
        }
        __syncthreads();

        const __nv_bfloat16* sAc = sA + cur * PJ_ST;
        const __nv_bfloat16* sBc = sB + cur * PJ_ST;
#pragma unroll
        for (int ks = 0; ks < 4; ++ks) {
            uint32_t af[2][4];
#pragma unroll
            for (int mt = 0; mt < 2; ++mt) {
                const int row = wr * 32 + mt * 16 + (lane & 7) + ((lane >> 3) & 1) * 8;
                const int col = ks * 16 + (lane >> 4) * 8;
                ldsm_x4(smem_u32(&sAc[row * 72 + col]), af[mt][0], af[mt][1], af[mt][2], af[mt][3]);
            }
#pragma unroll
            for (int g = 0; g < 4; ++g) {
                const int row = wc * 64 + g * 16 + (lane & 7) + (lane >> 4) * 8;
                const int col = ks * 16 + ((lane >> 3) & 1) * 8;
                uint32_t b0, b1, b2, b3;
                ldsm_x4(smem_u32(&sBc[row * 72 + col]), b0, b1, b2, b3);
#pragma unroll
                for (int mt = 0; mt < 2; ++mt) {
                    mma16816(acc[mt][2 * g],     af[mt], b0, b1);
                    mma16816(acc[mt][2 * g + 1], af[mt], b2, b3);
                }
            }
        }
        __syncthreads();
    }

#pragma unroll
    for (int mt = 0; mt < 2; ++mt) {
        const int row = mblk * 128 + wr * 32 + mt * 16 + (lane >> 2);
#pragma unroll
        for (int t = 0; t < 8; ++t) {
            const int col = nblk * 128 + wc * 64 + t * 8 + (lane & 3) * 2;
            *(uint32_t*)&dst[(size_t)row * FF + col] =
                packbf(acc[mt][t][0] * scale, acc[mt][t][1] * scale);
            *(uint32_t*)&dst[(size_t)(row + 8) * FF + col] =
                packbf(acc[mt][t][2] * scale, acc[mt][t][3] * scale);
        }
    }
}

// ---------------------------------------------------------------------------
// Fused flash attention: adj via coalesced cp.async through smem.
// grid=(32,8), 256 threads (8 warps x 16 q rows), 2 CTAs/SM.
// smem (110592 B): sK[2][64][72] bf16 @0, sV[2][64][72] bf16 @18432,
//                  sAdj[2][128][72] int @36864 (72-int stride, 2-way LDS).
// adj loader: 16 threads per 256 B row -> 4 x 128B lines per cp instruction.
// Per tile: wait(group jt) -> SYNC1 -> compute (mask from smem) -> SYNC2 ->
//           issue group jt+2 into the just-freed stage.
// ---------------------------------------------------------------------------
#define KST 9216                      // 64*72*2
#define SV_OFF (2 * KST)              // 18432
#define SA_OFF (4 * KST)              // 36864
#define AST (128 * 72 * 4)            // 36864 per adj stage
#define ATTN_SMEM (SA_OFF + 2 * AST)  // 110592

__global__ __launch_bounds__(256, 2) void attn_kernel(const float* __restrict__ x,
                                                      const int* __restrict__ adj,
                                                      float* __restrict__ out) {
    extern __shared__ char sm[];
    __nv_bfloat16* sK = (__nv_bfloat16*)sm;                // [2][64][72]
    __nv_bfloat16* sV = (__nv_bfloat16*)(sm + SV_OFF);     // [2][64][72]
    int*           sA = (int*)(sm + SA_OFF);               // [2][128][72]

    const int tid = threadIdx.x;
    const int lane = tid & 31;
    const int warp = tid >> 5;
    const int q0 = blockIdx.x * 128;
    const int h = blockIdx.y;
    const int hc = h * HD;

    const int lr = tid >> 3;           // 0..31
    const int lc8 = (tid & 7) * 8;     // 0..56

    // --- stage Q (128 x 64, stride 72) through the adj area, grab frags ---
    {
        __nv_bfloat16* sQ = (__nv_bfloat16*)(sm + SA_OFF);
#pragma unroll
        for (int p = 0; p < 4; ++p) {
            const int r = lr + p * 32;
            uint4 v = *(const uint4*)(g_Q + (size_t)(q0 + r) * FF + hc + lc8);
            *(uint4*)&sQ[r * 72 + lc8] = v;
        }
    }
    __syncthreads();

    const int rw = warp * 16;
    uint32_t qf[4][4];
    {
        __nv_bfloat16* sQ = (__nv_bfloat16*)(sm + SA_OFF);
#pragma unroll
        for (int ks = 0; ks < 4; ++ks) {
            const int row = rw + (lane & 7) + ((lane >> 3) & 1) * 8;
            const int col = ks * 16 + (lane >> 4) * 8;
            ldsm_x4(smem_u32(&sQ[row * 72 + col]), qf[ks][0], qf[ks][1], qf[ks][2], qf[ks][3]);
        }
    }
    __syncthreads();   // Q frags extracted; adj area free

    float O[8][4];
#pragma unroll
    for (int t = 0; t < 8; ++t)
#pragma unroll
        for (int i = 0; i < 4; ++i) O[t][i] = 0.f;

    float l0 = 0.f, l1 = 0.f;

    const int ci = lane & 3;
    const int rl0 = rw + (lane >> 2);
    const int r0g = q0 + rl0;

    // adj loader mapping: 16 threads per row, 16 B contiguous chunks.
    const int arow16 = tid >> 4;        // 0..15
    const int achk = tid & 15;          // 0..15 (x16 B)
    const int* adjBase = adj + ((size_t)h * NN + q0) * NN;   // row-major [128][NN]

    // combined loader: K/V tile (4 cp) + adj tile (8 cp) in ONE commit group
    auto load_group = [&](int st, int jt) {
        const int j0 = jt * 64;
        __nv_bfloat16* sKs = sK + st * (64 * 72);
        __nv_bfloat16* sVs = sV + st * (64 * 72);
#pragma unroll
        for (int p = 0; p < 2; ++p) {
            const int r = lr + p * 32;
            cp16(&sKs[r * 72 + lc8], g_K + (size_t)(j0 + r) * FF + hc + lc8);
            cp16(&sVs[r * 72 + lc8], g_V + (size_t)(j0 + r) * FF + hc + lc8);
        }
        int* sAs = sA + st * (128 * 72);
#pragma unroll
        for (int p = 0; p < 8; ++p) {
            const int r = arow16 + p * 16;      // 0..127
            cp16(sAs + r * 72 + achk * 4,
                 adjBase + (size_t)r * NN + j0 + achk * 4);
        }
        cp_commit();
    };

    // prologue: tiles 0 and 1
    load_group(0, 0);
    load_group(1, 1);

    for (int jt = 0; jt < 64; ++jt) {
        const int cur = jt & 1;

        if (jt < 63) cp_wait<1>();
        else         cp_wait<0>();
        __syncthreads();   // SYNC1: stage cur fully loaded, visible to all

        const __nv_bfloat16* sKc = sK + cur * (64 * 72);
        const __nv_bfloat16* sVc = sV + cur * (64 * 72);
        const int* sAc = sA + cur * (128 * 72);

        // S = Q K^T (base-2 scaled via Q)
        float s[8][4];
#pragma unroll
        for (int t = 0; t < 8; ++t)
#pragma unroll
            for (int i = 0; i < 4; ++i) s[t][i] = 0.f;

#pragma unroll
        for (int ks = 0; ks < 4; ++ks) {
#pragma unroll
            for (int g = 0; g < 4; ++g) {
                const int row = g * 16 + (lane & 7) + (lane >> 4) * 8;
                const int col = ks * 16 + ((lane >> 3) & 1) * 8;
                uint32_t b0, b1, b2, b3;
                ldsm_x4(smem_u32(&sKc[row * 72 + col]), b0, b1, b2, b3);
                mma16816(s[2 * g],     qf[ks], b0, b1);
                mma16816(s[2 * g + 1], qf[ks], b2, b3);
            }
        }

        // p = adj>0 ? exp2(s) : 0 ; accumulate per-lane l  (masks from smem)
        const int* a0base = sAc + rl0 * 72;
        const int* a1base = a0base + 8 * 72;
#pragma unroll
        for (int t = 0; t < 8; ++t) {
            int2 a0 = *(const int2*)(a0base + t * 8 + ci * 2);
            int2 a1 = *(const int2*)(a1base + t * 8 + ci * 2);
            float p00 = ex2(s[t][0]);
            float p01 = ex2(s[t][1]);
            float p10 = ex2(s[t][2]);
            float p11 = ex2(s[t][3]);
            p00 = (a0.x > 0) ? p00 : 0.f;
            p01 = (a0.y > 0) ? p01 : 0.f;
            p10 = (a1.x > 0) ? p10 : 0.f;
            p11 = (a1.y > 0) ? p11 : 0.f;
            l0 += p00 + p01;
            l1 += p10 + p11;
            s[t][0] = p00; s[t][1] = p01; s[t][2] = p10; s[t][3] = p11;
        }

        // O += P @ V
#pragma unroll
        for (int kg = 0; kg < 4; ++kg) {
            uint32_t pa[4];
            pa[0] = packbf(s[2 * kg][0],     s[2 * kg][1]);
            pa[1] = packbf(s[2 * kg][2],     s[2 * kg][3]);
            pa[2] = packbf(s[2 * kg + 1][0], s[2 * kg + 1][1]);
            pa[3] = packbf(s[2 * kg + 1][2], s[2 * kg + 1][3]);
#pragma unroll
            for (int dg = 0; dg < 4; ++dg) {
                const int row = kg * 16 + (lane & 7) + ((lane >> 3) & 1) * 8;
                const int col = dg * 16 + (lane >> 4) * 8;
                uint32_t b0, b1, b2, b3;
                ldsm_x4_t(smem_u32(&sVc[row * 72 + col]), b0, b1, b2, b3);
                mma16816(O[2 * dg],     pa, b0, b1);
                mma16816(O[2 * dg + 1], pa, b2, b3);
            }
        }

        __syncthreads();   // SYNC2: stage cur consumed by ALL warps
        if (jt + 2 < 64) load_group(cur, jt + 2);   // refill the freed stage
    }

    // reduce l over the quad, then epilogue: normalize, residual, ELU
    l0 += __shfl_xor_sync(0xffffffffu, l0, 1);
    l0 += __shfl_xor_sync(0xffffffffu, l0, 2);
    l1 += __shfl_xor_sync(0xffffffffu, l1, 1);
    l1 += __shfl_xor_sync(0xffffffffu, l1, 2);
    const float inv0 = 1.f / l0;
    const float inv1 = 1.f / l1;
    const int r0 = r0g;
    const int r1 = r0 + 8;
#pragma unroll
    for (int t = 0; t < 8; ++t) {
        const int col = hc + t * 8 + ci * 2;
        float2 x0 = *(const float2*)(x + (size_t)r0 * FF + col);
        float2 x1 = *(const float2*)(x + (size_t)r1 * FF + col);
        float v00 = O[t][0] * inv0 + x0.x;
        float v01 = O[t][1] * inv0 + x0.y;
        float v10 = O[t][2] * inv1 + x1.x;
        float v11 = O[t][3] * inv1 + x1.y;
        v00 = (v00 > 0.f) ? v00 : expm1f(v00);
        v01 = (v01 > 0.f) ? v01 : expm1f(v01);
        v10 = (v10 > 0.f) ? v10 : expm1f(v10);
        v11 = (v11 > 0.f) ? v11 : expm1f(v11);
        *(float2*)(out + (size_t)r0 * FF + col) = make_float2(v00, v01);
        *(float2*)(out + (size_t)r1 * FF + col) = make_float2(v10, v11);
    }
}

extern "C" void kernel_launch(void* const* d_in, const int* in_sizes, int n_in,
                              void* d_out, int out_size) {
    const float* x  = (const float*)d_in[0];
    const float* Wq = (const float*)d_in[1];
    const float* Wk = (const float*)d_in[2];
    const float* Wv = (const float*)d_in[3];
    const int* adj  = (const int*)d_in[4];
    float* out = (float*)d_out;

    cudaFuncSetAttribute(proj_kernel, cudaFuncAttributeMaxDynamicSharedMemorySize, PROJ_SMEM);
    cudaFuncSetAttribute(attn_kernel, cudaFuncAttributeMaxDynamicSharedMemorySize, ATTN_SMEM);

    cvt_kernel<<<2816, 256>>>(x, Wq, Wk, Wv);
    proj_kernel<<<dim3(32, 12), 256, PROJ_SMEM>>>();
    attn_kernel<<<dim3(32, 8), 256, ATTN_SMEM>>>(x, adj, out);
}

// round 14
// speedup vs baseline: 1.1049x; 1.0088x over previous
#include <cuda_runtime.h>
#include <cuda_bf16.h>
#include <cstdint>

// ---------------------------------------------------------------------------
// GraphAttentionLayer: N=4096, F=512, H=8, d=64
//  1) cvt_kernel:  x, Wq/Wk/Wv f32 -> bf16 globals (MLP-4 grid-stride)
//  2) proj_kernel: Q/K/V bf16 GEMM (cp.async 2-stage)
//  3) attn_kernel: flash attention; adj streamed via cp.async.bulk 256B row
//     copies into a 2-stage smem ring (mbarrier complete_tx), K/V on cp.async
//     commit groups, fixed-max base-2 softmax.
// ---------------------------------------------------------------------------

#define NN 4096
#define FF 512
#define NH 8
#define HD 64

__device__ __nv_bfloat16 g_Q[NN * FF];
__device__ __nv_bfloat16 g_K[NN * FF];
__device__ __nv_bfloat16 g_V[NN * FF];
__device__ __nv_bfloat16 g_xb[NN * FF];
__device__ __nv_bfloat16 g_Wb[3 * FF * FF];

__device__ __forceinline__ uint32_t smem_u32(const void* p) {
    return (uint32_t)__cvta_generic_to_shared(p);
}
__device__ __forceinline__ void ldsm_x4(uint32_t addr, uint32_t& r0, uint32_t& r1,
                                        uint32_t& r2, uint32_t& r3) {
    asm volatile("ldmatrix.sync.aligned.m8n8.x4.shared.b16 {%0,%1,%2,%3}, [%4];"
                 : "=r"(r0), "=r"(r1), "=r"(r2), "=r"(r3) : "r"(addr));
}
__device__ __forceinline__ void ldsm_x4_t(uint32_t addr, uint32_t& r0, uint32_t& r1,
                                          uint32_t& r2, uint32_t& r3) {
    asm volatile("ldmatrix.sync.aligned.m8n8.x4.trans.shared.b16 {%0,%1,%2,%3}, [%4];"
                 : "=r"(r0), "=r"(r1), "=r"(r2), "=r"(r3) : "r"(addr));
}
__device__ __forceinline__ void mma16816(float* d, const uint32_t* a, uint32_t b0, uint32_t b1) {
    asm volatile("mma.sync.aligned.m16n8k16.row.col.f32.bf16.bf16.f32 "
                 "{%0,%1,%2,%3}, {%4,%5,%6,%7}, {%8,%9}, {%0,%1,%2,%3};"
                 : "+f"(d[0]), "+f"(d[1]), "+f"(d[2]), "+f"(d[3])
                 : "r"(a[0]), "r"(a[1]), "r"(a[2]), "r"(a[3]), "r"(b0), "r"(b1));
}
__device__ __forceinline__ uint32_t packbf(float lo, float hi) {
    uint32_t r;
    asm("cvt.rn.bf16x2.f32 %0, %1, %2;" : "=r"(r) : "f"(hi), "f"(lo));
    return r;
}
__device__ __forceinline__ float ex2(float x) {
    float r;
    asm("ex2.approx.ftz.f32 %0, %1;" : "=f"(r) : "f"(x));
    return r;
}
__device__ __forceinline__ void cp16(void* s, const void* g) {
    asm volatile("cp.async.cg.shared.global [%0], [%1], 16;"
                 :: "r"(smem_u32(s)), "l"(g));
}
__device__ __forceinline__ void cp_commit() { asm volatile("cp.async.commit_group;"); }
template <int n>
__device__ __forceinline__ void cp_wait() { asm volatile("cp.async.wait_group %0;" :: "n"(n)); }

// 1D bulk copy global->shared with mbarrier completion
__device__ __forceinline__ void cp_bulk(uint32_t dst_smem, const void* src,
                                        uint32_t bytes, uint32_t mbar) {
    asm volatile("cp.async.bulk.shared::cta.global.mbarrier::complete_tx::bytes "
                 "[%0], [%1], %2, [%3];"
                 :: "r"(dst_smem), "l"(src), "r"(bytes), "r"(mbar) : "memory");
}
#define MBAR_INIT(mb, c) \
    asm volatile("mbarrier.init.shared.b64 [%0], %1;" :: "r"((uint32_t)(mb)), "r"((uint32_t)(c)) : "memory")
#define MBAR_EXPECT_TX(mb, bytes) \
    asm volatile("mbarrier.arrive.expect_tx.shared.b64 _, [%0], %1;" \
                 :: "r"((uint32_t)(mb)), "r"((uint32_t)(bytes)) : "memory")
#define MBAR_WAIT(mb, par) do {                                                      \
    uint32_t _m = (uint32_t)(mb); uint32_t _p = (uint32_t)(par); uint32_t _d;        \
    asm volatile("{\n\t.reg .pred p;\n\t"                                            \
        "mbarrier.try_wait.parity.acquire.cta.shared::cta.b64 p, [%1], %2;\n\t"      \
        "selp.b32 %0, 1, 0, p;\n\t}" : "=r"(_d) : "r"(_m), "r"(_p) : "memory");      \
    if (!_d) {                                                                       \
        asm volatile("{\n\t.reg .pred P1;\n\t"                                       \
            "WL_%=:\n\t"                                                             \
            "mbarrier.try_wait.parity.acquire.cta.shared::cta.b64 P1, [%0], %1, 0x989680;\n\t" \
            "@P1 bra.uni WD_%=;\n\t"                                                 \
            "bra.uni WL_%=;\n\t"                                                     \
            "WD_%=:\n\t}" :: "r"(_m), "r"(_p) : "memory");                           \
    }                                                                                \
} while (0)

// ---------------------------------------------------------------------------
// cvt: f32 -> bf16, 4 independent float4 per thread (MLP 4).
// ---------------------------------------------------------------------------
#define XN4 (NN * FF / 4)
#define WN4 (FF * FF / 4)
#define CVT_TOTAL (XN4 + 3 * WN4)       // 720896
#define CVT_BLOCKS 704                  // 704*256*4 = 720896

__global__ __launch_bounds__(256) void cvt_kernel(const float* __restrict__ x,
                                                  const float* __restrict__ Wq,
                                                  const float* __restrict__ Wk,
                                                  const float* __restrict__ Wv) {
    const int stride = CVT_BLOCKS * 256;
    const int i0 = blockIdx.x * 256 + threadIdx.x;

    const float* srcs[4];
    uint2* dsts[4];
    float4 v[4];
#pragma unroll
    for (int u = 0; u < 4; ++u) {
        const int i = i0 + u * stride;
        const float* src;
        __nv_bfloat16* dst;
        int off;
        if (i < XN4) {
            src = x; dst = g_xb; off = i;
        } else {
            const int j = i - XN4;
            const int m = j / WN4;
            off = j - m * WN4;
            src = (m == 0) ? Wq : (m == 1) ? Wk : Wv;
            dst = g_Wb + m * (FF * FF);
        }
        srcs[u] = (const float*)((const float4*)src + off);
        dsts[u] = (uint2*)dst + off;
    }
#pragma unroll
    for (int u = 0; u < 4; ++u) v[u] = __ldg((const float4*)srcs[u]);
#pragma unroll
    for (int u = 0; u < 4; ++u) {
        uint2 st;
        st.x = packbf(v[u].x, v[u].y);
        st.y = packbf(v[u].z, v[u].w);
        *dsts[u] = st;
    }
}

// ---------------------------------------------------------------------------
// Projection GEMM (bf16): tile 128x128x64, cp.async 2-stage. grid (32,12).
// ---------------------------------------------------------------------------
#define PJ_ST (128 * 72)
#define PROJ_SMEM (4 * PJ_ST * 2)

__global__ __launch_bounds__(256) void proj_kernel() {
    extern __shared__ __nv_bfloat16 ps[];
    __nv_bfloat16* sA = ps;
    __nv_bfloat16* sB = ps + 2 * PJ_ST;

    const int tid = threadIdx.x;
    const int lane = tid & 31;
    const int warp = tid >> 5;
    const int wr = warp & 3;
    const int wc = warp >> 2;
    const int mblk = blockIdx.x;
    const int mat = blockIdx.y >> 2;
    const int nblk = blockIdx.y & 3;

    const __nv_bfloat16* Ab = g_xb + (size_t)(mblk * 128) * FF;
    const __nv_bfloat16* Bb = g_Wb + (size_t)mat * FF * FF + (size_t)(nblk * 128) * FF;
    __nv_bfloat16* dst = (mat == 0) ? g_Q : (mat == 1) ? g_K : g_V;
    // Q scale = 1/sqrt(512) * log2(e)   (softmax in base-2)
    const float scale = (mat == 0) ? (0.044194173824159216f * 1.4426950408889634f) : 1.0f;

    float acc[2][8][4];
#pragma unroll
    for (int mt = 0; mt < 2; ++mt)
#pragma unroll
        for (int t = 0; t < 8; ++t)
#pragma unroll
            for (int i = 0; i < 4; ++i) acc[mt][t][i] = 0.f;

    const int lr = tid >> 3;
    const int lc8 = (tid & 7) * 8;

    auto load_tile = [&](int st, int kt) {
        const int k0 = kt * 64;
#pragma unroll
        for (int p = 0; p < 4; ++p) {
            const int r = lr + p * 32;
            cp16(&sA[st * PJ_ST + r * 72 + lc8], Ab + (size_t)r * FF + k0 + lc8);
            cp16(&sB[st * PJ_ST + r * 72 + lc8], Bb + (size_t)r * FF + k0 + lc8);
        }
        cp_commit();
    };

    load_tile(0, 0);

    for (int kt = 0; kt < 8; ++kt) {
        const int cur = kt & 1;
        if (kt < 7) {
            load_tile(cur ^ 1, kt + 1);
            cp_wait<1>();
        } else {
            cp_wait<0>();
        }
        __syncthreads();

        const __nv_bfloat16* sAc = sA + cur * PJ_ST;
        const __nv_bfloat16* sBc = sB + cur * PJ_ST;
#pragma unroll
        for (int ks = 0; ks < 4; ++ks) {
            uint32_t af[2][4];
#pragma unroll
            for (int mt = 0; mt < 2; ++mt) {
                const int row = wr * 32 + mt * 16 + (lane & 7) + ((lane >> 3) & 1) * 8;
                const int col = ks * 16 + (lane >> 4) * 8;
                ldsm_x4(smem_u32(&sAc[row * 72 + col]), af[mt][0], af[mt][1], af[mt][2], af[mt][3]);
            }
#pragma unroll
            for (int g = 0; g < 4; ++g) {
                const int row = wc * 64 + g * 16 + (lane & 7) + (lane >> 4) * 8;
                const int col = ks * 16 + ((lane >> 3) & 1) * 8;
                uint32_t b0, b1, b2, b3;
                ldsm_x4(smem_u32(&sBc[row * 72 + col]), b0, b1, b2, b3);
#pragma unroll
                for (int mt = 0; mt < 2; ++mt) {
                    mma16816(acc[mt][2 * g],     af[mt], b0, b1);
                    mma16816(acc[mt][2 * g + 1], af[mt], b2, b3);
                }
            }
        }
        __syncthreads();
    }

#pragma unroll
    for (int mt = 0; mt < 2; ++mt) {
        const int row = mblk * 128 + wr * 32 + mt * 16 + (lane >> 2);
#pragma unroll
        for (int t = 0; t < 8; ++t) {
            const int col = nblk * 128 + wc * 64 + t * 8 + (lane & 3) * 2;
            *(uint32_t*)&dst[(size_t)row * FF + col] =
                packbf(acc[mt][t][0] * scale, acc[mt][t][1] * scale);
            *(uint32_t*)&dst[(size_t)(row + 8) * FF + col] =
                packbf(acc[mt][t][2] * scale, acc[mt][t][3] * scale);
        }
    }
}

// ---------------------------------------------------------------------------
// Fused flash attention: adj via cp.async.bulk row copies (mbarrier), K/V via
// cp.async commit groups. grid=(32,8), 256 threads, 2 CTAs/SM.
// smem (110592 B): sK[2][64][72] bf16 @0, sV[2][64][72] @18432,
//                  sAdj[2][128][72] int @36864.
// Per tile: cp_wait(K/V) + MBAR_WAIT(adj) -> SYNC1 -> compute ->
//           expect_tx(next) -> SYNC2 -> issue K/V cp + adj bulk rows.
// ---------------------------------------------------------------------------
#define KST 9216
#define SV_OFF (2 * KST)              // 18432
#define SA_OFF (4 * KST)              // 36864
#define AST (128 * 72 * 4)            // 36864 per adj stage
#define ADJ_TILE_BYTES 32768          // 128 rows x 256 B
#define ATTN_SMEM (SA_OFF + 2 * AST)  // 110592

__global__ __launch_bounds__(256, 2) void attn_kernel(const float* __restrict__ x,
                                                      const int* __restrict__ adj,
                                                      float* __restrict__ out) {
    extern __shared__ char sm[];
    __nv_bfloat16* sK = (__nv_bfloat16*)sm;                // [2][64][72]
    __nv_bfloat16* sV = (__nv_bfloat16*)(sm + SV_OFF);     // [2][64][72]
    int*           sA = (int*)(sm + SA_OFF);               // [2][128][72]
    __shared__ __align__(8) uint64_t s_mbar[2];

    const uint32_t mb[2] = { smem_u32(&s_mbar[0]), smem_u32(&s_mbar[1]) };

    const int tid = threadIdx.x;
    const int lane = tid & 31;
    const int warp = tid >> 5;
    const int q0 = blockIdx.x * 128;
    const int h = blockIdx.y;
    const int hc = h * HD;

    const int lr = tid >> 3;           // 0..31
    const int lc8 = (tid & 7) * 8;     // 0..56

    if (tid == 0) {
        MBAR_INIT(mb[0], 1);
        MBAR_INIT(mb[1], 1);
    }

    // --- stage Q (128 x 64, stride 72) through the adj area, grab frags ---
    {
        __nv_bfloat16* sQ = (__nv_bfloat16*)(sm + SA_OFF);
#pragma unroll
        for (int p = 0; p < 4; ++p) {
            const int r = lr + p * 32;
            uint4 v = *(const uint4*)(g_Q + (size_t)(q0 + r) * FF + hc + lc8);
            *(uint4*)&sQ[r * 72 + lc8] = v;
        }
    }
    __syncthreads();

    const int rw = warp * 16;
    uint32_t qf[4][4];
    {
        __nv_bfloat16* sQ = (__nv_bfloat16*)(sm + SA_OFF);
#pragma unroll
        for (int ks = 0; ks < 4; ++ks) {
            const int row = rw + (lane & 7) + ((lane >> 3) & 1) * 8;
            const int col = ks * 16 + (lane >> 4) * 8;
            ldsm_x4(smem_u32(&sQ[row * 72 + col]), qf[ks][0], qf[ks][1], qf[ks][2], qf[ks][3]);
        }
    }

    // expect_tx for the two prologue adj tiles (mbar init is visible: the
    // __syncthreads above orders init before this point)
    if (tid == 0) {
        MBAR_EXPECT_TX(mb[0], ADJ_TILE_BYTES);
        MBAR_EXPECT_TX(mb[1], ADJ_TILE_BYTES);
    }
    __syncthreads();   // Q frags extracted; adj area free; expects visible

    float O[8][4];
#pragma unroll
    for (int t = 0; t < 8; ++t)
#pragma unroll
        for (int i = 0; i < 4; ++i) O[t][i] = 0.f;

    float l0 = 0.f, l1 = 0.f;

    const int ci = lane & 3;
    const int rl0 = rw + (lane >> 2);
    const int r0g = q0 + rl0;

    const int* adjBase = adj + ((size_t)h * NN + q0) * NN;   // [128][NN]

    auto load_kv = [&](int st, int jt) {
        const int j0 = jt * 64;
        __nv_bfloat16* sKs = sK + st * (64 * 72);
        __nv_bfloat16* sVs = sV + st * (64 * 72);
#pragma unroll
        for (int p = 0; p < 2; ++p) {
            const int r = lr + p * 32;
            cp16(&sKs[r * 72 + lc8], g_K + (size_t)(j0 + r) * FF + hc + lc8);
            cp16(&sVs[r * 72 + lc8], g_V + (size_t)(j0 + r) * FF + hc + lc8);
        }
        cp_commit();
    };
    auto load_adj = [&](int st, int jt) {
        // threads 0..127: one 256 B row each, completing on mb[st]
        if (tid < 128) {
            const int j0 = jt * 64;
            uint32_t dst = smem_u32(sA + st * (128 * 72) + tid * 72);
            cp_bulk(dst, adjBase + (size_t)tid * NN + j0, 256, mb[st]);
        }
    };

    // prologue: tiles 0 and 1
    load_kv(0, 0);
    load_kv(1, 1);
    load_adj(0, 0);
    load_adj(1, 1);

    for (int jt = 0; jt < 64; ++jt) {
        const int cur = jt & 1;

        if (jt < 63) cp_wait<1>();
        else         cp_wait<0>();
        MBAR_WAIT(mb[cur], (jt >> 1) & 1);
        __syncthreads();   // SYNC1: K/V + adj stage cur ready for all warps

        const __nv_bfloat16* sKc = sK + cur * (64 * 72);
        const __nv_bfloat16* sVc = sV + cur * (64 * 72);
        const int* sAc = sA + cur * (128 * 72);

        // S = Q K^T (base-2 scaled via Q)
        float s[8][4];
#pragma unroll
        for (int t = 0; t < 8; ++t)
#pragma unroll
            for (int i = 0; i < 4; ++i) s[t][i] = 0.f;

#pragma unroll
        for (int ks = 0; ks < 4; ++ks) {
#pragma unroll
            for (int g = 0; g < 4; ++g) {
                const int row = g * 16 + (lane & 7) + (lane >> 4) * 8;
                const int col = ks * 16 + ((lane >> 3) & 1) * 8;
                uint32_t b0, b1, b2, b3;
                ldsm_x4(smem_u32(&sKc[row * 72 + col]), b0, b1, b2, b3);
                mma16816(s[2 * g],     qf[ks], b0, b1);
                mma16816(s[2 * g + 1], qf[ks], b2, b3);
            }
        }

        // p = adj>0 ? exp2(s) : 0 ; accumulate per-lane l  (masks from smem)
        const int* a0base = sAc + rl0 * 72;
        const int* a1base = a0base + 8 * 72;
#pragma unroll
        for (int t = 0; t < 8; ++t) {
            int2 a0 = *(const int2*)(a0base + t * 8 + ci * 2);
            int2 a1 = *(const int2*)(a1base + t * 8 + ci * 2);
            float p00 = ex2(s[t][0]);
            float p01 = ex2(s[t][1]);
            float p10 = ex2(s[t][2]);
            float p11 = ex2(s[t][3]);
            p00 = (a0.x > 0) ? p00 : 0.f;
            p01 = (a0.y > 0) ? p01 : 0.f;
            p10 = (a1.x > 0) ? p10 : 0.f;
            p11 = (a1.y > 0) ? p11 : 0.f;
            l0 += p00 + p01;
            l1 += p10 + p11;
            s[t][0] = p00; s[t][1] = p01; s[t][2] = p10; s[t][3] = p11;
        }

        // O += P @ V
#pragma unroll
        for (int kg = 0; kg < 4; ++kg) {
            uint32_t pa[4];
            pa[0] = packbf(s[2 * kg][0],     s[2 * kg][1]);
            pa[1] = packbf(s[2 * kg][2],     s[2 * kg][3]);
            pa[2] = packbf(s[2 * kg + 1][0], s[2 * kg + 1][1]);
            pa[3] = packbf(s[2 * kg + 1][2], s[2 * kg + 1][3]);
#pragma unroll
            for (int dg = 0; dg < 4; ++dg) {
                const int row = kg * 16 + (lane & 7) + ((lane >> 3) & 1) * 8;
                const int col = dg * 16 + (lane >> 4) * 8;
                uint32_t b0, b1, b2, b3;
                ldsm_x4_t(smem_u32(&sVc[row * 72 + col]), b0, b1, b2, b3);
                mma16816(O[2 * dg],     pa, b0, b1);
                mma16816(O[2 * dg + 1], pa, b2, b3);
            }
        }

        // expect_tx for the refill of stage cur (ordered before bulk issues
        // by SYNC2; previous phase of mb[cur] completed at our wait above)
        if (tid == 0 && jt + 2 < 64) MBAR_EXPECT_TX(mb[cur], ADJ_TILE_BYTES);
        __syncthreads();   // SYNC2: stage cur consumed by ALL warps
        if (jt + 2 < 64) {
            load_kv(cur, jt + 2);
            load_adj(cur, jt + 2);
        }
    }

    // reduce l over the quad, then epilogue: normalize, residual, ELU
    l0 += __shfl_xor_sync(0xffffffffu, l0, 1);
    l0 += __shfl_xor_sync(0xffffffffu, l0, 2);
    l1 += __shfl_xor_sync(0xffffffffu, l1, 1);
    l1 += __shfl_xor_sync(0xffffffffu, l1, 2);
    const float inv0 = 1.f / l0;
    const float inv1 = 1.f / l1;
    const int r0 = r0g;
    const int r1 = r0 + 8;
#pragma unroll
    for (int t = 0; t < 8; ++t) {
        const int col = hc + t * 8 + ci * 2;
        float2 x0 = *(const float2*)(x + (size_t)r0 * FF + col);
        float2 x1 = *(const float2*)(x + (size_t)r1 * FF + col);
        float v00 = O[t][0] * inv0 + x0.x;
        float v01 = O[t][1] * inv0 + x0.y;
        float v10 = O[t][2] * inv1 + x1.x;
        float v11 = O[t][3] * inv1 + x1.y;
        v00 = (v00 > 0.f) ? v00 : expm1f(v00);
        v01 = (v01 > 0.f) ? v01 : expm1f(v01);
        v10 = (v10 > 0.f) ? v10 : expm1f(v10);
        v11 = (v11 > 0.f) ? v11 : expm1f(v11);
        *(float2*)(out + (size_t)r0 * FF + col) = make_float2(v00, v01);
        *(float2*)(out + (size_t)r1 * FF + col) = make_float2(v10, v11);
    }
}

extern "C" void kernel_launch(void* const* d_in, const int* in_sizes, int n_in,
                              void* d_out, int out_size) {
    const float* x  = (const float*)d_in[0];
    const float* Wq = (const float*)d_in[1];
    const float* Wk = (const float*)d_in[2];
    const float* Wv = (const float*)d_in[3];
    const int* adj  = (const int*)d_in[4];
    float* out = (float*)d_out;

    cudaFuncSetAttribute(proj_kernel, cudaFuncAttributeMaxDynamicSharedMemorySize, PROJ_SMEM);
    cudaFuncSetAttribute(attn_kernel, cudaFuncAttributeMaxDynamicSharedMemorySize, ATTN_SMEM);

    cvt_kernel<<<CVT_BLOCKS, 256>>>(x, Wq, Wk, Wv);
    proj_kernel<<<dim3(32, 12), 256, PROJ_SMEM>>>();
    attn_kernel<<<dim3(32, 8), 256, ATTN_SMEM>>>(x, adj, out);
}